// round 4
// baseline (speedup 1.0000x reference)
#include <cuda_runtime.h>
#include <cstdint>

// Problem constants
constexpr int NN = 100000;   // nodes
constexpr int NE = 1600000;  // edges
constexpr int NF = 128;      // input feats
constexpr int NC = 40;       // classes (post-projection feature width)

// ---------------- scratch (static device globals; no allocation) -------------
__device__ __align__(256) float d_deg[NN];
__device__ __align__(256) float d_dis[NN];
__device__ __align__(256) float d_norm[NE];
__device__ __align__(256) int2  d_rc[NE];
__device__ __align__(256) float d_hA[(size_t)NN * NC];
__device__ __align__(256) float d_hB[(size_t)NN * NC];

// ---------------- kernels ----------------------------------------------------

__global__ void zero_kernel(float4* __restrict__ p, int n4) {
    int i = blockIdx.x * blockDim.x + threadIdx.x;
    if (i < n4) p[i] = make_float4(0.f, 0.f, 0.f, 0.f);
}

// deg[col] += ew  (scatter over edges), guarded
__global__ void deg_kernel(const int* __restrict__ col,
                           const float* __restrict__ ew) {
    int e = blockIdx.x * blockDim.x + threadIdx.x;
    if (e < NE) {
        int c = col[e];
        if (c >= 0 && c < NN) atomicAdd(&d_deg[c], ew[e]);
    }
}

__global__ void dis_kernel() {
    int i = blockIdx.x * blockDim.x + threadIdx.x;
    if (i < NN) {
        float d = d_deg[i];
        d_dis[i] = (d > 0.0f) ? rsqrtf(d) : 0.0f;
    }
}

// norm[e] = dis[row]*ew*dis[col]; pack sanitized (row,col) into int2
__global__ void norm_kernel(const int* __restrict__ row,
                            const int* __restrict__ col,
                            const float* __restrict__ ew) {
    int e = blockIdx.x * blockDim.x + threadIdx.x;
    if (e < NE) {
        int r = row[e];
        int c = col[e];
        bool ok = (r >= 0 && r < NN && c >= 0 && c < NN);
        int ri = ok ? r : 0;
        int ci = ok ? c : 0;
        d_rc[e] = make_int2(ri, ci);
        d_norm[e] = ok ? (d_dis[ri] * ew[e] * d_dis[ci]) : 0.0f;
    }
}

// y[NN,40] = x[NN,128] @ W[128,40]
__global__ void xw_kernel(const float* __restrict__ x,
                          const float* __restrict__ W,
                          float* __restrict__ y) {
    __shared__ float sW[NF * NC];   // 20 KB
    __shared__ float sh[32][65];    // 8.3 KB (padded)
    int t = threadIdx.x;
    int nb = blockIdx.x * 64;

    for (int i = t; i < NF * NC; i += 128) sW[i] = W[i];

    int ng = t & 15;
    int cg = t >> 4;
    float acc[4][5] = {};

    for (int kc = 0; kc < NF; kc += 32) {
        __syncthreads();
        for (int i = t; i < 64 * 32; i += 128) {
            int n = i >> 5, k = i & 31;
            int node = nb + n;
            sh[k][n] = (node < NN) ? x[(size_t)node * NF + kc + k] : 0.0f;
        }
        __syncthreads();
        #pragma unroll 8
        for (int k = 0; k < 32; k++) {
            float hv[4], wv[5];
            #pragma unroll
            for (int i = 0; i < 4; i++) hv[i] = sh[k][ng * 4 + i];
            #pragma unroll
            for (int j = 0; j < 5; j++) wv[j] = sW[(kc + k) * NC + cg * 5 + j];
            #pragma unroll
            for (int i = 0; i < 4; i++)
                #pragma unroll
                for (int j = 0; j < 5; j++)
                    acc[i][j] += hv[i] * wv[j];
        }
    }
    #pragma unroll
    for (int i = 0; i < 4; i++) {
        int node = nb + ng * 4 + i;
        if (node < NN) {
            #pragma unroll
            for (int j = 0; j < 5; j++)
                y[(size_t)node * NC + cg * 5 + j] = acc[i][j];
        }
    }
}

// One hop: hout[col] += hin[row] * norm, feature width 40.
// Warp handles 32 edges: coalesced metadata load, then 16 iterations of
// 2 edges each (half-warp per edge, lanes 0-9 of each half do float4 = 40 floats).
__global__ void hop_kernel(const float* __restrict__ hin,
                           float* __restrict__ hout) {
    int warp = (blockIdx.x * blockDim.x + threadIdx.x) >> 5;
    int lane = threadIdx.x & 31;
    int base = warp * 32;
    if (base >= NE) return;

    int e = base + lane;
    int2 p = d_rc[e];          // NE % 32 == 0, always in range
    float w = d_norm[e];

    int sub  = lane & 15;   // lane within half-warp
    int half = lane >> 4;   // which edge of the pair

    #pragma unroll 4
    for (int j = 0; j < 32; j += 2) {
        int src = j + half;
        int r   = __shfl_sync(0xffffffffu, p.x, src);
        int c   = __shfl_sync(0xffffffffu, p.y, src);
        float wj = __shfl_sync(0xffffffffu, w, src);
        if (sub < 10) {
            const float4* sp = reinterpret_cast<const float4*>(hin + (size_t)r * NC) + sub;
            float4 v = __ldg(sp);
            v.x *= wj; v.y *= wj; v.z *= wj; v.w *= wj;
            float* dst = hout + (size_t)c * NC + sub * 4;
            asm volatile("red.global.add.v4.f32 [%0], {%1,%2,%3,%4};"
                         :: "l"(dst), "f"(v.x), "f"(v.y), "f"(v.z), "f"(v.w)
                         : "memory");
        }
    }
}

// ---------------- launch ------------------------------------------------------

extern "C" void kernel_launch(void* const* d_in, const int* in_sizes, int n_in,
                              void* d_out, int out_size) {
    // Resolve inputs BY ELEMENT COUNT (order-independent; all counts distinct):
    //   x: NN*NF = 12,800,000   edge_index: 2*NE = 3,200,000 (int32!)
    //   edge_weight: NE = 1,600,000   W: NF*NC = 5,120
    const float* x  = nullptr;
    const int*   ei = nullptr;
    const float* ew = nullptr;
    const float* W  = nullptr;
    for (int i = 0; i < n_in; i++) {
        long long sz = in_sizes[i];
        if      (sz == (long long)NN * NF) x  = (const float*)d_in[i];
        else if (sz == (long long)2 * NE)  ei = (const int*)d_in[i];
        else if (sz == (long long)NE)      ew = (const float*)d_in[i];
        else if (sz == (long long)NF * NC) W  = (const float*)d_in[i];
    }
    float* out = (float*)d_out;

    const int* row = ei;        // edge_index[0, :]
    const int* col = ei + NE;   // edge_index[1, :]

    float* deg;  cudaGetSymbolAddress((void**)&deg,  d_deg);
    float* hA;   cudaGetSymbolAddress((void**)&hA,   d_hA);
    float* hB;   cudaGetSymbolAddress((void**)&hB,   d_hB);

    const int ZT = 256;
    // 1) deg = scatter(ew by col)
    zero_kernel<<<(NN/4 + ZT - 1)/ZT, ZT>>>((float4*)deg, NN/4);
    deg_kernel<<<(NE + 255)/256, 256>>>(col, ew);
    // 2) deg_inv_sqrt
    dis_kernel<<<(NN + 255)/256, 256>>>();
    // 3) per-edge norm + packed indices
    norm_kernel<<<(NE + 255)/256, 256>>>(row, col, ew);
    // 4) project first: hA = x @ W  (valid since aggregation is linear)
    xw_kernel<<<(NN + 63)/64, 128>>>(x, W, hA);

    // 5) three hops, ping-pong; final hop writes straight to d_out
    const int HOP_BLOCKS = (NE/32 + 7) / 8;  // 8 warps/block, 32 edges/warp
    zero_kernel<<<(NN*NC/4 + ZT - 1)/ZT, ZT>>>((float4*)hB, NN*NC/4);
    hop_kernel<<<HOP_BLOCKS, 256>>>(hA, hB);

    zero_kernel<<<(NN*NC/4 + ZT - 1)/ZT, ZT>>>((float4*)hA, NN*NC/4);
    hop_kernel<<<HOP_BLOCKS, 256>>>(hB, hA);

    zero_kernel<<<(NN*NC/4 + ZT - 1)/ZT, ZT>>>((float4*)out, NN*NC/4);
    hop_kernel<<<HOP_BLOCKS, 256>>>(hA, out);
}